// round 14
// baseline (speedup 1.0000x reference)
#include <cuda_runtime.h>
#include <cuda_fp16.h>
#include <math.h>

#define WARPS_PER_BLOCK 8
#define THREADS_PER_BLOCK (WARPS_PER_BLOCK * 32)
#define FULL_MASK 0xffffffffu
#define MAX_NODES 100000
#define FEAT 64

// fp16 staging of node_value: one row = 64 halves = 128B = ONE L2 line.
__device__ uint4 g_value_h[(size_t)MAX_NODES * (FEAT / 8)];

// Index width (int32 vs int64) detected from raw words of row_ptr.
__device__ __forceinline__ long long load_index(const void* p, long long i, int is64)
{
    return is64 ? ((const long long*)p)[i] : (long long)((const int*)p)[i];
}

__device__ __forceinline__ void hfma2(unsigned& acc, unsigned v, unsigned w)
{
    asm("fma.rn.f16x2 %0, %1, %2, %0;" : "+r"(acc) : "r"(v), "r"(w));
}

// replicate low/high fp16 half of a b32 (PRMT, alu pipe)
__device__ __forceinline__ unsigned dup_lo(unsigned x)
{
    unsigned r;
    asm("prmt.b32 %0, %1, %1, 0x1010;" : "=r"(r) : "r"(x));
    return r;
}
__device__ __forceinline__ unsigned dup_hi(unsigned x)
{
    unsigned r;
    asm("prmt.b32 %0, %1, %1, 0x3232;" : "=r"(r) : "r"(x));
    return r;
}

__device__ __forceinline__ float2 h2f2(unsigned h)
{
    return __half22float2(*reinterpret_cast<const __half2*>(&h));
}

// PDL: wait for predecessor kernel (convert). No-op without PDL launch.
__device__ __forceinline__ void griddep_wait()
{
    asm volatile("griddepcontrol.wait;" ::: "memory");
}

__global__ void __launch_bounds__(512)
convert_to_half_kernel(const float4* __restrict__ node_value4, int n_u4)
{
    const int i = blockIdx.x * blockDim.x + threadIdx.x;
    if (i < n_u4) {
        const float4 fa = node_value4[2 * i];
        const float4 fb = node_value4[2 * i + 1];
        uint4 h;
        *reinterpret_cast<__half2*>(&h.x) = __floats2half2_rn(fa.x, fa.y);
        *reinterpret_cast<__half2*>(&h.y) = __floats2half2_rn(fa.z, fa.w);
        *reinterpret_cast<__half2*>(&h.z) = __floats2half2_rn(fb.x, fb.y);
        *reinterpret_cast<__half2*>(&h.w) = __floats2half2_rn(fb.z, fb.w);
        g_value_h[i] = h;
    }
}

// FOUR nodes per warp; softmax per 8-lane quarter; fp16 gather (1 line/edge);
// HFMA2 dual-chain accumulation. Hot loop is 2-stage software-pipelined:
// iteration e+1's shuffles + gathers are issued while iteration e's data is
// consumed -> 4 gather loads in flight per warp at ~75% occupancy.
__global__ void __launch_bounds__(THREADS_PER_BLOCK, 6)
gat_aggregate_kernel(const void*   __restrict__ row_ptr_raw,
                     const void*   __restrict__ col_idx_raw,
                     const float*  __restrict__ edge_scores,
                     const float4* __restrict__ node_value4,  // fp32 fallback
                     float4*       __restrict__ out4,         // [N, 16] float4
                     int num_nodes)
{
    const int quad  = blockIdx.x * WARPS_PER_BLOCK + (threadIdx.x >> 5);
    const int node0 = 4 * quad;
    if (node0 >= num_nodes) { griddep_wait(); return; }
    const int lane = threadIdx.x & 31;

    const unsigned* rp_raw = (const unsigned*)row_ptr_raw;
    const int is64 = (rp_raw[1] == 0u && rp_raw[2] != 0u) ? 1 : 0;

    bool fast = (node0 + 4 <= num_nodes) && (num_nodes <= MAX_NODES);
    long long r0 = 0;
    if (fast) {
        r0 = load_index(row_ptr_raw, node0, is64);
        const long long r4 = load_index(row_ptr_raw, node0 + 4, is64);
        const long long r1 = load_index(row_ptr_raw, node0 + 1, is64);
        const long long r2 = load_index(row_ptr_raw, node0 + 2, is64);
        const long long r3 = load_index(row_ptr_raw, node0 + 3, is64);
        fast = (r1 - r0 == 16) && (r2 - r1 == 16) && (r3 - r2 == 16) && (r4 - r3 == 16);
    }

    if (fast) {
        // ---- fast path: 4 nodes, all degree 16, fp16-staged gather ----
        const float2 s2 = *((const float2*)(edge_scores + r0) + lane);
        unsigned c0, c1;
        if (is64) {
            c0 = (unsigned)((const long long*)col_idx_raw)[r0 + 2 * lane];
            c1 = (unsigned)((const long long*)col_idx_raw)[r0 + 2 * lane + 1];
        } else {
            const int2 cc = *((const int2*)((const int*)col_idx_raw + r0) + lane);
            c0 = (unsigned)cc.x; c1 = (unsigned)cc.y;
        }

        // per-quarter softmax (8 lanes = 16 edges = one node)
        float m = fmaxf(s2.x, s2.y);
        #pragma unroll
        for (int off = 4; off > 0; off >>= 1)
            m = fmaxf(m, __shfl_xor_sync(FULL_MASK, m, off));

        float w0 = __expf(s2.x - m);
        float w1 = __expf(s2.y - m);
        float sum = w0 + w1;
        #pragma unroll
        for (int off = 4; off > 0; off >>= 1)
            sum += __shfl_xor_sync(FULL_MASK, sum, off);
        const float inv = __frcp_rn(sum);

        // pack both normalized weights into ONE f16x2 register:
        // low half = w0, high half = w1
        unsigned wp;
        {
            const float a = w0 * inv, b = w1 * inv;
            asm("cvt.rn.f16x2.f32 %0, %2, %1;" : "=r"(wp) : "f"(a), "f"(b));
        }

        const int qbase = lane & 0x18;
        const int sub8  = lane & 7;
        const char* vbase = (const char*)g_value_h + (sub8 << 4);

        // convert-independent work done; wait for converted table (PDL)
        griddep_wait();

        unsigned aA0 = 0, aA1 = 0, aA2 = 0, aA3 = 0;
        unsigned aB0 = 0, aB1 = 0, aB2 = 0, aB3 = 0;

        // ---- 2-stage software pipeline over 8 edge-pair iterations ----
        uint4 hA, hB;          // in-flight data for current iteration
        unsigned whA, whB;     // current weights (fp16x2 splat)
        {
            const unsigned bcA = __shfl_sync(FULL_MASK, c0, qbase);
            const unsigned bcB = __shfl_sync(FULL_MASK, c1, qbase);
            const unsigned bwp = __shfl_sync(FULL_MASK, wp, qbase);
            hA = *(const uint4*)(vbase + ((size_t)bcA << 7));
            hB = *(const uint4*)(vbase + ((size_t)bcB << 7));
            whA = dup_lo(bwp);
            whB = dup_hi(bwp);
        }

        #pragma unroll
        for (int e8 = 0; e8 < 8; e8++) {
            uint4 nA, nB;
            unsigned nwA, nwB;
            if (e8 < 7) {
                const int src = qbase + e8 + 1;
                const unsigned bcA = __shfl_sync(FULL_MASK, c0, src);
                const unsigned bcB = __shfl_sync(FULL_MASK, c1, src);
                const unsigned bwp = __shfl_sync(FULL_MASK, wp, src);
                nA = *(const uint4*)(vbase + ((size_t)bcA << 7));
                nB = *(const uint4*)(vbase + ((size_t)bcB << 7));
                nwA = dup_lo(bwp);
                nwB = dup_hi(bwp);
            }

            // consume current (loads issued one iteration ago)
            hfma2(aA0, hA.x, whA);
            hfma2(aA1, hA.y, whA);
            hfma2(aA2, hA.z, whA);
            hfma2(aA3, hA.w, whA);
            hfma2(aB0, hB.x, whB);
            hfma2(aB1, hB.y, whB);
            hfma2(aB2, hB.z, whB);
            hfma2(aB3, hB.w, whB);

            if (e8 < 7) {
                hA = nA; hB = nB; whA = nwA; whB = nwB;
            }
        }

        const float2 fA0 = h2f2(aA0), fB0 = h2f2(aB0);
        const float2 fA1 = h2f2(aA1), fB1 = h2f2(aB1);
        const float2 fA2 = h2f2(aA2), fB2 = h2f2(aB2);
        const float2 fA3 = h2f2(aA3), fB3 = h2f2(aB3);

        const int node = node0 + (lane >> 3);
        const size_t ob = (size_t)node * 16 + sub8 * 2;
        out4[ob]     = make_float4(fA0.x + fB0.x, fA0.y + fB0.y,
                                   fA1.x + fB1.x, fA1.y + fB1.y);
        out4[ob + 1] = make_float4(fA2.x + fB2.x, fA2.y + fB2.y,
                                   fA3.x + fB3.x, fA3.y + fB3.y);
    } else {
        // ---- generic path: any degree, full fp32 (not taken here) ----
        griddep_wait();
        const int half = lane >> 4;
        const int sub  = lane & 15;
        for (int which = 0; which < 4; which++) {
            const int node = node0 + which;
            if (node >= num_nodes) break;
            const long long s0 = load_index(row_ptr_raw, node, is64);
            const long long s1 = load_index(row_ptr_raw, node + 1, is64);
            const int deg = (int)(s1 - s0);

            float m = -INFINITY;
            for (int e = lane; e < deg; e += 32)
                m = fmaxf(m, edge_scores[s0 + e]);
            #pragma unroll
            for (int off = 16; off > 0; off >>= 1)
                m = fmaxf(m, __shfl_xor_sync(FULL_MASK, m, off));

            float sum = 0.0f;
            for (int e = lane; e < deg; e += 32)
                sum += __expf(edge_scores[s0 + e] - m);
            #pragma unroll
            for (int off = 16; off > 0; off >>= 1)
                sum += __shfl_xor_sync(FULL_MASK, sum, off);
            const float inv = (deg > 0) ? __frcp_rn(sum) : 0.0f;

            float4 acc = make_float4(0.0f, 0.0f, 0.0f, 0.0f);
            for (int e = 0; e < deg; e++) {
                const float bs = edge_scores[s0 + e];
                const unsigned bc = (unsigned)load_index(col_idx_raw, s0 + e, is64);
                const float bw = __expf(bs - m) * inv;
                const float4 v = node_value4[(size_t)bc * 16 + sub];
                acc.x = fmaf(bw, v.x, acc.x);
                acc.y = fmaf(bw, v.y, acc.y);
                acc.z = fmaf(bw, v.z, acc.z);
                acc.w = fmaf(bw, v.w, acc.w);
            }
            if (half == 0)
                out4[(size_t)node * 16 + sub] = acc;
        }
    }
}

extern "C" void kernel_launch(void* const* d_in, const int* in_sizes, int n_in,
                              void* d_out, int out_size)
{
    const void*   row_ptr     = d_in[0];
    const void*   col_idx     = d_in[1];
    const float*  edge_scores = (const float*)d_in[2];
    const float4* node_value4 = (const float4*)d_in[3];
    float4*       out4        = (float4*)d_out;

    const int num_nodes = in_sizes[0] - 1;
    const int n_u4 = in_sizes[3] / 8;

    if (num_nodes <= MAX_NODES)
        convert_to_half_kernel<<<(n_u4 + 511) / 512, 512>>>(node_value4, n_u4);

    const int num_quads = (num_nodes + 3) / 4;
    const int grid = (num_quads + WARPS_PER_BLOCK - 1) / WARPS_PER_BLOCK;

    // PDL: main kernel's prologue overlaps the convert kernel's tail.
    cudaLaunchConfig_t cfg = {};
    cfg.gridDim  = dim3(grid, 1, 1);
    cfg.blockDim = dim3(THREADS_PER_BLOCK, 1, 1);
    cfg.dynamicSmemBytes = 0;
    cfg.stream = 0;
    cudaLaunchAttribute attrs[1];
    attrs[0].id = cudaLaunchAttributeProgrammaticStreamSerialization;
    attrs[0].val.programmaticStreamSerializationAllowed = 1;
    cfg.attrs = attrs;
    cfg.numAttrs = 1;

    cudaLaunchKernelEx(&cfg, gat_aggregate_kernel,
                       row_ptr, col_idx, edge_scores, node_value4, out4,
                       num_nodes);
}

// round 15
// speedup vs baseline: 1.0112x; 1.0112x over previous
#include <cuda_runtime.h>
#include <cuda_fp16.h>
#include <math.h>

#define WARPS_PER_BLOCK 8
#define THREADS_PER_BLOCK (WARPS_PER_BLOCK * 32)
#define FULL_MASK 0xffffffffu
#define MAX_NODES 100000
#define FEAT 64

// fp16 staging of node_value: one row = 64 halves = 128B = ONE L2 line.
__device__ uint4 g_value_h[(size_t)MAX_NODES * (FEAT / 8)];

// Index width (int32 vs int64) detected from raw words of row_ptr:
//   int32: [0, D, 2D, ...]  -> raw[1] != 0
//   int64: [0,0, D,0, ...]  -> raw[1] == 0 && raw[2] != 0
__device__ __forceinline__ long long load_index(const void* p, long long i, int is64)
{
    return is64 ? ((const long long*)p)[i] : (long long)((const int*)p)[i];
}

__device__ __forceinline__ void hfma2(unsigned& acc, unsigned v, unsigned w)
{
    asm("fma.rn.f16x2 %0, %1, %2, %0;" : "+r"(acc) : "r"(v), "r"(w));
}

__device__ __forceinline__ unsigned splat_h2(float w)
{
    unsigned r;
    asm("cvt.rn.f16x2.f32 %0, %1, %1;" : "=r"(r) : "f"(w));
    return r;
}

__device__ __forceinline__ float2 h2f2(unsigned h)
{
    return __half22float2(*reinterpret_cast<const __half2*>(&h));
}

// PDL: dependent waits for predecessor's release (or completion).
__device__ __forceinline__ void griddep_wait()
{
    asm volatile("griddepcontrol.wait;" ::: "memory");
}
// PDL: predecessor releases dependents early; stores issued before this by
// each thread are visible to the dependent grid after its wait.
__device__ __forceinline__ void griddep_launch_dependents()
{
    asm volatile("griddepcontrol.launch_dependents;" ::: "memory");
}

__global__ void __launch_bounds__(512)
convert_to_half_kernel(const float4* __restrict__ node_value4, int n_u4)
{
    const int i = blockIdx.x * blockDim.x + threadIdx.x;
    if (i < n_u4) {
        const float4 fa = node_value4[2 * i];
        const float4 fb = node_value4[2 * i + 1];
        uint4 h;
        *reinterpret_cast<__half2*>(&h.x) = __floats2half2_rn(fa.x, fa.y);
        *reinterpret_cast<__half2*>(&h.y) = __floats2half2_rn(fa.z, fa.w);
        *reinterpret_cast<__half2*>(&h.z) = __floats2half2_rn(fb.x, fb.y);
        *reinterpret_cast<__half2*>(&h.w) = __floats2half2_rn(fb.z, fb.w);
        g_value_h[i] = h;
    }
    // Release the dependent grid as soon as our stores are done (all threads
    // execute this; the release fires when every block has signaled/exited),
    // cutting grid-teardown latency out of the critical path.
    griddep_launch_dependents();
}

// FOUR nodes per warp (64 contiguous CSR edges). Lane loads one float2
// score-pair + col-pair. Softmax per 8-lane quarter (butterfly 4,2,1).
// Gather: quarter q serves node 4p+q; lane owns 8 features (uint4 fp16);
// edge-pair iterations keep 2 gathers in flight. HFMA2 dual-chain
// accumulation merged in fp32. PDL dependent of the convert kernel.
__global__ void __launch_bounds__(THREADS_PER_BLOCK, 7)
gat_aggregate_kernel(const void*   __restrict__ row_ptr_raw,
                     const void*   __restrict__ col_idx_raw,
                     const float*  __restrict__ edge_scores,
                     const float4* __restrict__ node_value4,  // fp32 fallback
                     float4*       __restrict__ out4,         // [N, 16] float4
                     int num_nodes)
{
    const int quad  = blockIdx.x * WARPS_PER_BLOCK + (threadIdx.x >> 5);
    const int node0 = 4 * quad;
    if (node0 >= num_nodes) { griddep_wait(); return; }
    const int lane = threadIdx.x & 31;

    const unsigned* rp_raw = (const unsigned*)row_ptr_raw;
    const int is64 = (rp_raw[1] == 0u && rp_raw[2] != 0u) ? 1 : 0;

    bool fast = (node0 + 4 <= num_nodes) && (num_nodes <= MAX_NODES);
    long long r0 = 0;
    if (fast) {
        r0 = load_index(row_ptr_raw, node0, is64);
        const long long r4 = load_index(row_ptr_raw, node0 + 4, is64);
        const long long r1 = load_index(row_ptr_raw, node0 + 1, is64);
        const long long r2 = load_index(row_ptr_raw, node0 + 2, is64);
        const long long r3 = load_index(row_ptr_raw, node0 + 3, is64);
        fast = (r1 - r0 == 16) && (r2 - r1 == 16) && (r3 - r2 == 16) && (r4 - r3 == 16);
    }

    if (fast) {
        // ---- fast path: 4 nodes, all degree 16, fp16-staged gather ----
        const float2 s2 = *((const float2*)(edge_scores + r0) + lane);
        unsigned c0, c1;
        if (is64) {
            c0 = (unsigned)((const long long*)col_idx_raw)[r0 + 2 * lane];
            c1 = (unsigned)((const long long*)col_idx_raw)[r0 + 2 * lane + 1];
        } else {
            const int2 cc = *((const int2*)((const int*)col_idx_raw + r0) + lane);
            c0 = (unsigned)cc.x; c1 = (unsigned)cc.y;
        }

        // per-quarter softmax (8 lanes = 16 edges = one node)
        float m = fmaxf(s2.x, s2.y);
        #pragma unroll
        for (int off = 4; off > 0; off >>= 1)
            m = fmaxf(m, __shfl_xor_sync(FULL_MASK, m, off));

        float w0 = __expf(s2.x - m);
        float w1 = __expf(s2.y - m);
        float sum = w0 + w1;
        #pragma unroll
        for (int off = 4; off > 0; off >>= 1)
            sum += __shfl_xor_sync(FULL_MASK, sum, off);
        const float inv = __frcp_rn(sum);
        w0 *= inv; w1 *= inv;

        const int qbase = lane & 0x18;          // quarter base lane
        const int sub8  = lane & 7;             // uint4 slot within the row
        const char* vbase = (const char*)g_value_h + (sub8 << 4);

        // convert-independent work done; wait for converted table (PDL)
        griddep_wait();

        // two independent fp16 accumulation chains (8 terms each)
        unsigned aA0 = 0, aA1 = 0, aA2 = 0, aA3 = 0;
        unsigned aB0 = 0, aB1 = 0, aB2 = 0, aB3 = 0;

        #pragma unroll
        for (int e8 = 0; e8 < 8; e8++) {
            const int src = qbase + e8;
            const float    bwA = __shfl_sync(FULL_MASK, w0, src);
            const unsigned bcA = __shfl_sync(FULL_MASK, c0, src);
            const float    bwB = __shfl_sync(FULL_MASK, w1, src);
            const unsigned bcB = __shfl_sync(FULL_MASK, c1, src);

            // both loads issued before either is consumed (MLP >= 2)
            const uint4 hA = *(const uint4*)(vbase + ((size_t)bcA << 7));
            const uint4 hB = *(const uint4*)(vbase + ((size_t)bcB << 7));

            const unsigned whA = splat_h2(bwA);
            const unsigned whB = splat_h2(bwB);

            hfma2(aA0, hA.x, whA);
            hfma2(aA1, hA.y, whA);
            hfma2(aA2, hA.z, whA);
            hfma2(aA3, hA.w, whA);

            hfma2(aB0, hB.x, whB);
            hfma2(aB1, hB.y, whB);
            hfma2(aB2, hB.z, whB);
            hfma2(aB3, hB.w, whB);
        }

        // merge the two chains in fp32
        const float2 fA0 = h2f2(aA0), fB0 = h2f2(aB0);
        const float2 fA1 = h2f2(aA1), fB1 = h2f2(aB1);
        const float2 fA2 = h2f2(aA2), fB2 = h2f2(aB2);
        const float2 fA3 = h2f2(aA3), fB3 = h2f2(aB3);

        const int node = node0 + (lane >> 3);
        const size_t ob = (size_t)node * 16 + sub8 * 2;
        out4[ob]     = make_float4(fA0.x + fB0.x, fA0.y + fB0.y,
                                   fA1.x + fB1.x, fA1.y + fB1.y);
        out4[ob + 1] = make_float4(fA2.x + fB2.x, fA2.y + fB2.y,
                                   fA3.x + fB3.x, fA3.y + fB3.y);
    } else {
        // ---- generic path: any degree, full fp32 (not taken here) ----
        griddep_wait();
        const int half = lane >> 4;
        const int sub  = lane & 15;
        for (int which = 0; which < 4; which++) {
            const int node = node0 + which;
            if (node >= num_nodes) break;
            const long long s0 = load_index(row_ptr_raw, node, is64);
            const long long s1 = load_index(row_ptr_raw, node + 1, is64);
            const int deg = (int)(s1 - s0);

            float m = -INFINITY;
            for (int e = lane; e < deg; e += 32)
                m = fmaxf(m, edge_scores[s0 + e]);
            #pragma unroll
            for (int off = 16; off > 0; off >>= 1)
                m = fmaxf(m, __shfl_xor_sync(FULL_MASK, m, off));

            float sum = 0.0f;
            for (int e = lane; e < deg; e += 32)
                sum += __expf(edge_scores[s0 + e] - m);
            #pragma unroll
            for (int off = 16; off > 0; off >>= 1)
                sum += __shfl_xor_sync(FULL_MASK, sum, off);
            const float inv = (deg > 0) ? __frcp_rn(sum) : 0.0f;

            float4 acc = make_float4(0.0f, 0.0f, 0.0f, 0.0f);
            for (int e = 0; e < deg; e++) {
                const float bs = edge_scores[s0 + e];
                const unsigned bc = (unsigned)load_index(col_idx_raw, s0 + e, is64);
                const float bw = __expf(bs - m) * inv;
                const float4 v = node_value4[(size_t)bc * 16 + sub];
                acc.x = fmaf(bw, v.x, acc.x);
                acc.y = fmaf(bw, v.y, acc.y);
                acc.z = fmaf(bw, v.z, acc.z);
                acc.w = fmaf(bw, v.w, acc.w);
            }
            if (half == 0)
                out4[(size_t)node * 16 + sub] = acc;
        }
    }
}

extern "C" void kernel_launch(void* const* d_in, const int* in_sizes, int n_in,
                              void* d_out, int out_size)
{
    const void*   row_ptr     = d_in[0];
    const void*   col_idx     = d_in[1];
    const float*  edge_scores = (const float*)d_in[2];
    const float4* node_value4 = (const float4*)d_in[3];
    float4*       out4        = (float4*)d_out;

    const int num_nodes = in_sizes[0] - 1;
    const int n_u4 = in_sizes[3] / 8;

    if (num_nodes <= MAX_NODES)
        convert_to_half_kernel<<<(n_u4 + 511) / 512, 512>>>(node_value4, n_u4);

    const int num_quads = (num_nodes + 3) / 4;
    const int grid = (num_quads + WARPS_PER_BLOCK - 1) / WARPS_PER_BLOCK;

    // PDL: main kernel's prologue overlaps the convert kernel; convert
    // releases dependents early via griddepcontrol.launch_dependents.
    cudaLaunchConfig_t cfg = {};
    cfg.gridDim  = dim3(grid, 1, 1);
    cfg.blockDim = dim3(THREADS_PER_BLOCK, 1, 1);
    cfg.dynamicSmemBytes = 0;
    cfg.stream = 0;
    cudaLaunchAttribute attrs[1];
    attrs[0].id = cudaLaunchAttributeProgrammaticStreamSerialization;
    attrs[0].val.programmaticStreamSerializationAllowed = 1;
    cfg.attrs = attrs;
    cfg.numAttrs = 1;

    cudaLaunchKernelEx(&cfg, gat_aggregate_kernel,
                       row_ptr, col_idx, edge_scores, node_value4, out4,
                       num_nodes);
}